// round 14
// baseline (speedup 1.0000x reference)
#include <cuda_runtime.h>
#include <cuda_fp16.h>
#include <cstdint>

#define NH 8
#define HD 64
#define NB 4
#define NSEQ 1024
#define CQ 512

// ---------------- static scratch (no allocations allowed) ----------------
__device__ __align__(16) __half g_x16[NB * NSEQ * CQ];        // fp16 input
__device__ __align__(16) __half g_w16[5 * CQ * CQ];           // Wq,Wk,Wv,Wg,Wo fp16
__device__ __align__(16) __half g_q16[NB * NH * NSEQ * HD];   // [B,H,N,D] pre-scaled
__device__ __align__(16) __half g_k16[NB * NH * NSEQ * HD];
__device__ __align__(16) __half g_v16[NB * NH * NSEQ * HD];
__device__ __align__(16) __half g_o16[NB * NSEQ * CQ];        // attention out [B,N,H*D]
__device__ float g_gate[NB * NSEQ * CQ];                      // sigmoid gate (fp32)

// ---------------- helpers ----------------
__device__ __forceinline__ void ldm4(uint32_t& r0, uint32_t& r1, uint32_t& r2, uint32_t& r3,
                                     uint32_t addr) {
    asm volatile("ldmatrix.sync.aligned.m8n8.x4.shared.b16 {%0,%1,%2,%3}, [%4];"
                 : "=r"(r0), "=r"(r1), "=r"(r2), "=r"(r3)
                 : "r"(addr));
}
__device__ __forceinline__ void ldm4t(uint32_t& r0, uint32_t& r1, uint32_t& r2, uint32_t& r3,
                                      uint32_t addr) {
    asm volatile("ldmatrix.sync.aligned.m8n8.x4.trans.shared.b16 {%0,%1,%2,%3}, [%4];"
                 : "=r"(r0), "=r"(r1), "=r"(r2), "=r"(r3)
                 : "r"(addr));
}
__device__ __forceinline__ void mma16(float* c, const uint32_t* a, const uint32_t* b) {
    asm volatile(
        "mma.sync.aligned.m16n8k16.row.col.f32.f16.f16.f32 "
        "{%0,%1,%2,%3}, {%4,%5,%6,%7}, {%8,%9}, {%0,%1,%2,%3};"
        : "+f"(c[0]), "+f"(c[1]), "+f"(c[2]), "+f"(c[3])
        : "r"(a[0]), "r"(a[1]), "r"(a[2]), "r"(a[3]), "r"(b[0]), "r"(b[1]));
}
__device__ __forceinline__ void cp16(uint32_t dst, const void* src) {
    asm volatile("cp.async.cg.shared.global [%0], [%1], 16;\n" ::"r"(dst), "l"(src));
}
__device__ __forceinline__ void cp_commit() { asm volatile("cp.async.commit_group;\n"); }
template <int N>
__device__ __forceinline__ void cp_wait() { asm volatile("cp.async.wait_group %0;\n" ::"n"(N)); }

__device__ __forceinline__ uint32_t h2u(__half2 h) { return *reinterpret_cast<uint32_t*>(&h); }

// ---------------- 0) fp32 -> fp16 conversion pass ----------------
__global__ __launch_bounds__(256) void convert_kernel(const float* __restrict__ x,
                                                      const float* __restrict__ wq,
                                                      const float* __restrict__ wk,
                                                      const float* __restrict__ wv,
                                                      const float* __restrict__ wg,
                                                      const float* __restrict__ wo) {
    const int z = blockIdx.y;
    const float* src;
    __half* dst;
    int cnt;
    if (z == 0) { src = x; dst = g_x16; cnt = NB * NSEQ * CQ; }
    else if (z == 1) { src = wq; dst = g_w16; cnt = CQ * CQ; }
    else if (z == 2) { src = wk; dst = g_w16 + CQ * CQ; cnt = CQ * CQ; }
    else if (z == 3) { src = wv; dst = g_w16 + 2 * CQ * CQ; cnt = CQ * CQ; }
    else if (z == 4) { src = wg; dst = g_w16 + 3 * CQ * CQ; cnt = CQ * CQ; }
    else { src = wo; dst = g_w16 + 4 * CQ * CQ; cnt = CQ * CQ; }
    const int idx = (blockIdx.x * 256 + threadIdx.x) * 8;
    if (idx < cnt) {
        float4 v0 = *reinterpret_cast<const float4*>(src + idx);
        float4 v1 = *reinterpret_cast<const float4*>(src + idx + 4);
        __half2* d2 = reinterpret_cast<__half2*>(dst + idx);
        d2[0] = __floats2half2_rn(v0.x, v0.y);
        d2[1] = __floats2half2_rn(v0.z, v0.w);
        d2[2] = __floats2half2_rn(v1.x, v1.y);
        d2[3] = __floats2half2_rn(v1.z, v1.w);
    }
}

#define GSTR 72
#define GA_BYTES (128 * GSTR * 2)  // 18432
#define GB_BYTES (64 * GSTR * 2)   // 9216

// ---------------- paired GEMM core: shared A, two B matrices ----------------
#define PS_STG (GA_BYTES + 2 * GB_BYTES)  // 36864
#define PROJ_SMEM (2 * PS_STG)            // 73728

__device__ __forceinline__ void gemm_pair(const __half* __restrict__ A,
                                          const __half* __restrict__ B0,
                                          const __half* __restrict__ B1, int row0, int col0,
                                          float* acc0, float* acc1, __half* dsm) {
    const int tid = threadIdx.x, lane = tid & 31, wid = tid >> 5;
    const int wm = (wid >> 1) << 5, wn = (wid & 1) << 5;
    const int mi = lane >> 3;
    const uint32_t sb = (uint32_t)__cvta_generic_to_shared(dsm);

#pragma unroll
    for (int i = 0; i < 32; i++) {
        acc0[i] = 0.f;
        acc1[i] = 0.f;
    }

    const int lr = tid >> 3, lch = tid & 7;
    const __half* aSrc = A + (size_t)(row0 + lr) * CQ + lch * 8;
    const __half* b0Src = B0 + (size_t)(col0 + lr) * CQ + lch * 8;
    const __half* b1Src = B1 + (size_t)(col0 + lr) * CQ + lch * 8;
    const uint32_t sAd = (lr * GSTR + lch * 8) * 2;

    auto issue = [&](int stage, int kt) {
        const int k0 = kt << 6;
        const uint32_t ab = sb + stage * PS_STG;
#pragma unroll
        for (int t = 0; t < 4; t++)
            cp16(ab + sAd + t * 32 * GSTR * 2, aSrc + (size_t)t * 32 * CQ + k0);
#pragma unroll
        for (int t = 0; t < 2; t++)
            cp16(ab + GA_BYTES + sAd + t * 32 * GSTR * 2, b0Src + (size_t)t * 32 * CQ + k0);
#pragma unroll
        for (int t = 0; t < 2; t++)
            cp16(ab + GA_BYTES + GB_BYTES + sAd + t * 32 * GSTR * 2,
                 b1Src + (size_t)t * 32 * CQ + k0);
        cp_commit();
    };

    issue(0, 0);
    issue(1, 1);

    for (int kt = 0; kt < 8; kt++) {
        cp_wait<0>();
        __syncthreads();
        if (kt + 1 < 8) issue((kt + 1) & 1, kt + 1);

        const uint32_t ab = sb + (kt & 1) * PS_STG;
        const uint32_t b0b = ab + GA_BYTES;
        const uint32_t b1b = ab + GA_BYTES + GB_BYTES;
#pragma unroll
        for (int ks = 0; ks < 4; ks++) {
            uint32_t a[2][4], b0[2][4], b1[2][4];
#pragma unroll
            for (int mf = 0; mf < 2; mf++) {
                int row = wm + mf * 16 + (lane & 7) + ((mi & 1) << 3);
                int kch = ks * 2 + (mi >> 1);
                ldm4(a[mf][0], a[mf][1], a[mf][2], a[mf][3], ab + (row * GSTR + kch * 8) * 2);
            }
#pragma unroll
            for (int g = 0; g < 2; g++) {
                int row = wn + g * 16 + (lane & 7) + ((mi >> 1) << 3);
                int kch = ks * 2 + (mi & 1);
                ldm4(b0[g][0], b0[g][1], b0[g][2], b0[g][3], b0b + (row * GSTR + kch * 8) * 2);
                ldm4(b1[g][0], b1[g][1], b1[g][2], b1[g][3], b1b + (row * GSTR + kch * 8) * 2);
            }
#pragma unroll
            for (int mf = 0; mf < 2; mf++)
#pragma unroll
                for (int g = 0; g < 2; g++) {
                    mma16(acc0 + (mf * 4 + g * 2) * 4, a[mf], b0[g]);
                    mma16(acc0 + (mf * 4 + g * 2 + 1) * 4, a[mf], b0[g] + 2);
                    mma16(acc1 + (mf * 4 + g * 2) * 4, a[mf], b1[g]);
                    mma16(acc1 + (mf * 4 + g * 2 + 1) * 4, a[mf], b1[g] + 2);
                }
        }
        __syncthreads();
    }
    cp_wait<0>();
}

// ---------------- single GEMM core (for final), S=2, 3 CTA/SM ----------------
#define GS 2
#define GEMM_SMEM (GS * (GA_BYTES + GB_BYTES))  // 55296 B

__device__ __forceinline__ void gemm128x64h(const __half* __restrict__ A, int lda,
                                            const __half* __restrict__ Bp, int ldb, int K,
                                            int row0, int col0, float* acc, __half* dsm) {
    const int tid = threadIdx.x, lane = tid & 31, wid = tid >> 5;
    const int wm = (wid >> 1) << 5, wn = (wid & 1) << 5;
    const int mi = lane >> 3;
    const uint32_t sb = (uint32_t)__cvta_generic_to_shared(dsm);
    const int NK = K >> 6;

#pragma unroll
    for (int i = 0; i < 32; i++) acc[i] = 0.f;

    const int lr = tid >> 3, lch = tid & 7;
    const __half* aSrc = A + (size_t)(row0 + lr) * lda + lch * 8;
    const __half* bSrc = Bp + (size_t)(col0 + lr) * ldb + lch * 8;
    const uint32_t sAd = (lr * GSTR + lch * 8) * 2;

    auto issue = [&](int stage, int kt) {
        const int k0 = kt << 6;
        const uint32_t ab = sb + stage * GA_BYTES;
        const uint32_t bb = sb + GS * GA_BYTES + stage * GB_BYTES;
#pragma unroll
        for (int t = 0; t < 4; t++)
            cp16(ab + sAd + t * 32 * GSTR * 2, aSrc + (size_t)t * 32 * lda + k0);
#pragma unroll
        for (int t = 0; t < 2; t++)
            cp16(bb + sAd + t * 32 * GSTR * 2, bSrc + (size_t)t * 32 * ldb + k0);
        cp_commit();
    };

    issue(0, 0);
    issue(1, 1);

    for (int kt = 0; kt < NK; kt++) {
        cp_wait<GS - 2>();
        __syncthreads();
        if (kt + GS - 1 < NK) issue((kt + GS - 1) & 1, kt + GS - 1);

        const uint32_t ab = sb + (kt & 1) * GA_BYTES;
        const uint32_t bb = sb + GS * GA_BYTES + (kt & 1) * GB_BYTES;
#pragma unroll
        for (int ks = 0; ks < 4; ks++) {
            uint32_t a[2][4], b[2][4];
#pragma unroll
            for (int mf = 0; mf < 2; mf++) {
                int row = wm + mf * 16 + (lane & 7) + ((mi & 1) << 3);
                int kch = ks * 2 + (mi >> 1);
                ldm4(a[mf][0], a[mf][1], a[mf][2], a[mf][3], ab + (row * GSTR + kch * 8) * 2);
            }
#pragma unroll
            for (int g = 0; g < 2; g++) {
                int row = wn + g * 16 + (lane & 7) + ((mi >> 1) << 3);
                int kch = ks * 2 + (mi & 1);
                ldm4(b[g][0], b[g][1], b[g][2], b[g][3], bb + (row * GSTR + kch * 8) * 2);
            }
#pragma unroll
            for (int mf = 0; mf < 2; mf++)
#pragma unroll
                for (int g = 0; g < 2; g++) {
                    mma16(acc + (mf * 4 + g * 2) * 4, a[mf], b[g]);
                    mma16(acc + (mf * 4 + g * 2 + 1) * 4, a[mf], b[g] + 2);
                }
        }
        __syncthreads();
    }
    cp_wait<0>();
}

// ---------------- 1) paired Q/K and V/Gate projections ----------------
__global__ __launch_bounds__(256, 2) void proj_kernel(const float* __restrict__ bq,
                                                      const float* __restrict__ bg,
                                                      const float* __restrict__ gbias) {
    extern __shared__ __half hsm[];
    const int zp = blockIdx.z;
    const __half* B0 = g_w16 + (size_t)(zp * 2) * CQ * CQ;      // Wq or Wv
    const __half* B1 = g_w16 + (size_t)(zp * 2 + 1) * CQ * CQ;  // Wk or Wg
    const int row0 = blockIdx.y * 128, col0 = blockIdx.x * 64;
    float acc0[32], acc1[32];
    gemm_pair(g_x16, B0, B1, row0, col0, acc0, acc1, hsm);

    const int lane = threadIdx.x & 31, wid = threadIdx.x >> 5;
    const int wm = (wid >> 1) << 5, wn = (wid & 1) << 5;
#pragma unroll
    for (int m = 0; m < 2; m++)
#pragma unroll
        for (int n = 0; n < 4; n++) {
            const float* a0 = acc0 + (m * 4 + n) * 4;
            const float* a1 = acc1 + (m * 4 + n) * 4;
            const int r = row0 + wm + m * 16 + (lane >> 2);
            const int c = col0 + wn + n * 8 + ((lane & 3) << 1);
            const int b = r >> 10, nn0 = r & 1023, nn1 = (r + 8) & 1023;
            const int h = c >> 6, d = c & 63;
            if (zp == 0) {
                const float q0 = (a0[0] + bq[c]) * 0.125f;
                const float q1 = (a0[1] + bq[c + 1]) * 0.125f;
                const float q2 = (a0[2] + bq[c]) * 0.125f;
                const float q3 = (a0[3] + bq[c + 1]) * 0.125f;
                __half* qrow0 = g_q16 + ((size_t)((b * NH + h) * NSEQ) + nn0) * HD + d;
                __half* qrow1 = g_q16 + ((size_t)((b * NH + h) * NSEQ) + nn1) * HD + d;
                *reinterpret_cast<__half2*>(qrow0) = __floats2half2_rn(q0, q1);
                *reinterpret_cast<__half2*>(qrow1) = __floats2half2_rn(q2, q3);
                __half* krow0 = g_k16 + ((size_t)((b * NH + h) * NSEQ) + nn0) * HD + d;
                __half* krow1 = g_k16 + ((size_t)((b * NH + h) * NSEQ) + nn1) * HD + d;
                *reinterpret_cast<__half2*>(krow0) = __floats2half2_rn(a1[0], a1[1]);
                *reinterpret_cast<__half2*>(krow1) = __floats2half2_rn(a1[2], a1[3]);
            } else {
                __half* vrow0 = g_v16 + ((size_t)((b * NH + h) * NSEQ) + nn0) * HD + d;
                __half* vrow1 = g_v16 + ((size_t)((b * NH + h) * NSEQ) + nn1) * HD + d;
                *reinterpret_cast<__half2*>(vrow0) = __floats2half2_rn(a0[0], a0[1]);
                *reinterpret_cast<__half2*>(vrow1) = __floats2half2_rn(a0[2], a0[3]);
                const float bb = bg[c] + gbias[c], bb1 = bg[c + 1] + gbias[c + 1];
                float2 g0 = make_float2(1.f / (1.f + __expf(-(a1[0] + bb))),
                                        1.f / (1.f + __expf(-(a1[1] + bb1))));
                float2 g1 = make_float2(1.f / (1.f + __expf(-(a1[2] + bb))),
                                        1.f / (1.f + __expf(-(a1[3] + bb1))));
                *reinterpret_cast<float2*>(&g_gate[(size_t)r * CQ + c]) = g0;
                *reinterpret_cast<float2*>(&g_gate[(size_t)(r + 8) * CQ + c]) = g1;
            }
        }
}

// ---------------- 2) fused flash attention ----------------
// Double-buffered K/V via cp.async (issued at loop TOP -> full iteration of flight),
// bias read DIRECTLY from global into registers (no smem staging, identical fp32 math).
// smem: Q 18432 | K0 K1 | V0 V1 = 5 x 18432 = 92160 B -> 2 CTA/SM.
#define KV_BYTES (128 * 72 * 2)  // 18432
#define FL_K KV_BYTES            // after Q
#define FL_V (FL_K + 2 * KV_BYTES)
#define FLASH_SMEM (FL_V + 2 * KV_BYTES)  // 92160

__global__ __launch_bounds__(256, 2) void flash_kernel(const float* __restrict__ attn_bias) {
    extern __shared__ __half fs16[];
    const uint32_t sb = (uint32_t)__cvta_generic_to_shared(fs16);
    const uint32_t Qb = sb, Kb0 = sb + FL_K, Vb0 = sb + FL_V;

    const int bh = blockIdx.y;
    const int qt = blockIdx.x;
    const int b = bh >> 3, h = bh & 7;
    const int tid = threadIdx.x, lane = tid & 31, warp = tid >> 5;
    const int mi = lane >> 3;
    const int rl = lane >> 2;
    const __half* qptr = g_q16 + (size_t)bh * NSEQ * HD + (size_t)qt * 128 * HD;
    const __half* kptr = g_k16 + (size_t)bh * NSEQ * HD;
    const __half* vptr = g_v16 + (size_t)bh * NSEQ * HD;
    // per-thread bias row pointers (rows r0 and r0+8 of this q tile)
    const float* biasR0 = attn_bias + (size_t)bh * NSEQ * NSEQ +
                          (size_t)(qt * 128 + warp * 16 + rl) * NSEQ + ((lane & 3) << 1);
    const float* biasR1 = biasR0 + 8 * NSEQ;

    auto issueKV = [&](int buf, int kt) {
        const uint32_t kb = Kb0 + buf * KV_BYTES, vb = Vb0 + buf * KV_BYTES;
#pragma unroll
        for (int t = 0; t < 4; t++) {
            int idx = tid + t * 256;
            int r = idx >> 3, ch = idx & 7;
            cp16(kb + (r * 72 + ch * 8) * 2, kptr + (size_t)(kt * 128 + r) * HD + ch * 8);
        }
#pragma unroll
        for (int t = 0; t < 4; t++) {
            int idx = tid + t * 256;
            int r = idx >> 3, ch = idx & 7;
            cp16(vb + (r * 72 + ch * 8) * 2, vptr + (size_t)(kt * 128 + r) * HD + ch * 8);
        }
        cp_commit();
    };

    issueKV(0, 0);

    // prologue: Q tile -> smem -> fragments (own region, never overwritten)
#pragma unroll
    for (int t = 0; t < 4; t++) {
        int idx = tid + t * 256;
        int r = idx >> 3, ch = idx & 7;
        *reinterpret_cast<uint4*>(&fs16[r * 72 + ch * 8]) =
            *reinterpret_cast<const uint4*>(qptr + r * HD + ch * 8);
    }
    __syncthreads();

    uint32_t qf[4][4];
#pragma unroll
    for (int ks = 0; ks < 4; ks++) {
        int row = warp * 16 + (lane & 7) + ((mi & 1) << 3);
        int kch = ks * 2 + (mi >> 1);
        ldm4(qf[ks][0], qf[ks][1], qf[ks][2], qf[ks][3], Qb + (row * 72 + kch * 8) * 2);
    }

    float l0 = 0.f, l1 = 0.f;
    float acc_o[8][4];
#pragma unroll
    for (int n = 0; n < 8; n++)
#pragma unroll
        for (int j = 0; j < 4; j++) acc_o[n][j] = 0.f;

    for (int kt = 0; kt < 8; kt++) {
        cp_wait<0>();     // K/V tile kt landed (only outstanding group)
        __syncthreads();  // every warp finished reading buffer (kt+1)&1 in iter kt-1
        if (kt < 7) issueKV((kt + 1) & 1, kt + 1);  // full iteration of flight time

        const uint32_t Kb = Kb0 + (kt & 1) * KV_BYTES;
        const uint32_t Vb = Vb0 + (kt & 1) * KV_BYTES;

#pragma unroll
        for (int half = 0; half < 2; half++) {
            // S = Q K^T over 64 keys
            float s[8][4];
#pragma unroll
            for (int n = 0; n < 8; n++)
#pragma unroll
                for (int j = 0; j < 4; j++) s[n][j] = 0.f;
#pragma unroll
            for (int ks = 0; ks < 4; ks++) {
                const int kch = ks * 2 + (mi & 1);
#pragma unroll
                for (int nb = 0; nb < 4; nb++) {
                    uint32_t b0, b1, b2, b3;
                    int row = half * 64 + nb * 16 + (lane & 7) + ((mi >> 1) << 3);
                    ldm4(b0, b1, b2, b3, Kb + (row * 72 + kch * 8) * 2);
                    uint32_t bA[2] = {b0, b1}, bB[2] = {b2, b3};
                    mma16(s[2 * nb], qf[ks], bA);
                    mma16(s[2 * nb + 1], qf[ks], bB);
                }
            }

            // bias direct from gmem (two 8-load batches, MLP=8) + exp; P packed in regs
            const float* bc0 = biasR0 + kt * 128 + half * 64;
            const float* bc1 = biasR1 + kt * 128 + half * 64;
            uint32_t pf[4][4];
            float rs0 = 0.f, rs1 = 0.f;
#pragma unroll
            for (int batch = 0; batch < 2; batch++) {
                float2 bb0[4], bb1[4];
#pragma unroll
                for (int j = 0; j < 4; j++) {
                    const int c = (batch * 4 + j) * 8;
                    bb0[j] = *reinterpret_cast<const float2*>(bc0 + c);
                    bb1[j] = *reinterpret_cast<const float2*>(bc1 + c);
                }
#pragma unroll
                for (int j = 0; j < 4; j++) {
                    const int n = batch * 4 + j;
                    float p0 = __expf(s[n][0] + bb0[j].x);
                    float p1 = __expf(s[n][1] + bb0[j].y);
                    float p2 = __expf(s[n][2] + bb1[j].x);
                    float p3 = __expf(s[n][3] + bb1[j].y);
                    rs0 += p0 + p1;
                    rs1 += p2 + p3;
                    const uint32_t h01 = h2u(__floats2half2_rn(p0, p1));
                    const uint32_t h23 = h2u(__floats2half2_rn(p2, p3));
                    if ((n & 1) == 0) {
                        pf[n >> 1][0] = h01;
                        pf[n >> 1][1] = h23;
                    } else {
                        pf[n >> 1][2] = h01;
                        pf[n >> 1][3] = h23;
                    }
                }
            }
            l0 += rs0;
            l1 += rs1;

            // O += P V over these 64 keys
#pragma unroll
            for (int ks2 = 0; ks2 < 4; ks2++) {
                int srow = half * 64 + ks2 * 16 + (lane & 7) + ((mi & 1) << 3);
#pragma unroll
                for (int nb = 0; nb < 4; nb++) {
                    uint32_t b0, b1, b2, b3;
                    int nch = nb * 2 + (mi >> 1);
                    ldm4t(b0, b1, b2, b3, Vb + (srow * 72 + nch * 8) * 2);
                    uint32_t bA[2] = {b0, b1}, bB[2] = {b2, b3};
                    mma16(acc_o[2 * nb], pf[ks2], bA);
                    mma16(acc_o[2 * nb + 1], pf[ks2], bB);
                }
            }
        }
    }

    // final l reduction (4 lanes per row)
    l0 += __shfl_xor_sync(0xffffffffu, l0, 1);
    l0 += __shfl_xor_sync(0xffffffffu, l0, 2);
    l1 += __shfl_xor_sync(0xffffffffu, l1, 1);
    l1 += __shfl_xor_sync(0xffffffffu, l1, 2);

    const float inv0 = 1.f / l0, inv1 = 1.f / l1;
    const int qg = qt * 128 + warp * 16 + rl;
#pragma unroll
    for (int n = 0; n < 8; n++) {
        int c = h * HD + n * 8 + ((lane & 3) << 1);
        *reinterpret_cast<__half2*>(&g_o16[(size_t)(b * NSEQ + qg) * CQ + c]) =
            __floats2half2_rn(acc_o[n][0] * inv0, acc_o[n][1] * inv0);
        *reinterpret_cast<__half2*>(&g_o16[(size_t)(b * NSEQ + qg + 8) * CQ + c]) =
            __floats2half2_rn(acc_o[n][2] * inv1, acc_o[n][3] * inv1);
    }
}

// ---------------- 3) out = (o @ Wo^T + bo) * gate ----------------
__global__ __launch_bounds__(256, 3) void final_kernel(const float* __restrict__ bo,
                                                       float* __restrict__ out) {
    extern __shared__ __half hsm[];
    const int row0 = blockIdx.y * 128, col0 = blockIdx.x * 64;
    float acc[32];
    gemm128x64h(g_o16, CQ, g_w16 + 4 * CQ * CQ, CQ, CQ, row0, col0, acc, hsm);

    const int lane = threadIdx.x & 31, wid = threadIdx.x >> 5;
    const int wm = (wid >> 1) << 5, wn = (wid & 1) << 5;
#pragma unroll
    for (int m = 0; m < 2; m++)
#pragma unroll
        for (int n = 0; n < 4; n++) {
            const float* a4 = acc + (m * 4 + n) * 4;
            const int r = row0 + wm + m * 16 + (lane >> 2);
            const int c = col0 + wn + n * 8 + ((lane & 3) << 1);
            const float b0 = bo[c], b1 = bo[c + 1];
            float2 o0 = make_float2((a4[0] + b0) * g_gate[(size_t)r * CQ + c],
                                    (a4[1] + b1) * g_gate[(size_t)r * CQ + c + 1]);
            float2 o1 = make_float2((a4[2] + b0) * g_gate[(size_t)(r + 8) * CQ + c],
                                    (a4[3] + b1) * g_gate[(size_t)(r + 8) * CQ + c + 1]);
            *reinterpret_cast<float2*>(&out[(size_t)r * CQ + c]) = o0;
            *reinterpret_cast<float2*>(&out[(size_t)(r + 8) * CQ + c]) = o1;
        }
}

// ---------------- launch ----------------
extern "C" void kernel_launch(void* const* d_in, const int* in_sizes, int n_in,
                              void* d_out, int out_size) {
    const float* q_x = (const float*)d_in[0];
    const float* attn_bias = (const float*)d_in[1];
    const float* Wq = (const float*)d_in[2];
    const float* bq = (const float*)d_in[3];
    const float* Wk = (const float*)d_in[4];
    const float* Wv = (const float*)d_in[5];
    const float* Wo = (const float*)d_in[6];
    const float* bo = (const float*)d_in[7];
    const float* Wg = (const float*)d_in[8];
    const float* bg = (const float*)d_in[9];
    const float* gbias = (const float*)d_in[10];
    float* out = (float*)d_out;

    cudaFuncSetAttribute(flash_kernel, cudaFuncAttributeMaxDynamicSharedMemorySize, FLASH_SMEM);
    cudaFuncSetAttribute(proj_kernel, cudaFuncAttributeMaxDynamicSharedMemorySize, PROJ_SMEM);
    cudaFuncSetAttribute(final_kernel, cudaFuncAttributeMaxDynamicSharedMemorySize, GEMM_SMEM);

    convert_kernel<<<dim3(1024, 6), 256>>>(q_x, Wq, Wk, Wv, Wg, Wo);
    proj_kernel<<<dim3(CQ / 64, (NB * NSEQ) / 128, 2), 256, PROJ_SMEM>>>(bq, bg, gbias);
    flash_kernel<<<dim3(NSEQ / 128, NB * NH), 256, FLASH_SMEM>>>(attn_bias);
    final_kernel<<<dim3(CQ / 64, (NB * NSEQ) / 128), 256, GEMM_SMEM>>>(bo, out);
}

// round 16
// speedup vs baseline: 1.6638x; 1.6638x over previous
#include <cuda_runtime.h>
#include <cuda_fp16.h>
#include <cstdint>

#define NH 8
#define HD 64
#define NB 4
#define NSEQ 1024
#define CQ 512

// ---------------- static scratch (no allocations allowed) ----------------
__device__ __align__(16) __half g_x16[NB * NSEQ * CQ];        // fp16 input
__device__ __align__(16) __half g_w16[5 * CQ * CQ];           // Wq,Wk,Wv,Wg,Wo fp16
__device__ __align__(16) __half g_q16[NB * NH * NSEQ * HD];   // [B,H,N,D] pre-scaled
__device__ __align__(16) __half g_k16[NB * NH * NSEQ * HD];
__device__ __align__(16) __half g_v16[NB * NH * NSEQ * HD];
__device__ __align__(16) __half g_o16[NB * NSEQ * CQ];        // attention out [B,N,H*D]
__device__ float g_gate[NB * NSEQ * CQ];                      // sigmoid gate (fp32)

// ---------------- helpers ----------------
__device__ __forceinline__ void ldm4(uint32_t& r0, uint32_t& r1, uint32_t& r2, uint32_t& r3,
                                     uint32_t addr) {
    asm volatile("ldmatrix.sync.aligned.m8n8.x4.shared.b16 {%0,%1,%2,%3}, [%4];"
                 : "=r"(r0), "=r"(r1), "=r"(r2), "=r"(r3)
                 : "r"(addr));
}
__device__ __forceinline__ void ldm4t(uint32_t& r0, uint32_t& r1, uint32_t& r2, uint32_t& r3,
                                      uint32_t addr) {
    asm volatile("ldmatrix.sync.aligned.m8n8.x4.trans.shared.b16 {%0,%1,%2,%3}, [%4];"
                 : "=r"(r0), "=r"(r1), "=r"(r2), "=r"(r3)
                 : "r"(addr));
}
__device__ __forceinline__ void mma16(float* c, const uint32_t* a, const uint32_t* b) {
    asm volatile(
        "mma.sync.aligned.m16n8k16.row.col.f32.f16.f16.f32 "
        "{%0,%1,%2,%3}, {%4,%5,%6,%7}, {%8,%9}, {%0,%1,%2,%3};"
        : "+f"(c[0]), "+f"(c[1]), "+f"(c[2]), "+f"(c[3])
        : "r"(a[0]), "r"(a[1]), "r"(a[2]), "r"(a[3]), "r"(b[0]), "r"(b[1]));
}
__device__ __forceinline__ void cp16(uint32_t dst, const void* src) {
    asm volatile("cp.async.cg.shared.global [%0], [%1], 16;\n" ::"r"(dst), "l"(src));
}
__device__ __forceinline__ void cp_commit() { asm volatile("cp.async.commit_group;\n"); }
template <int N>
__device__ __forceinline__ void cp_wait() { asm volatile("cp.async.wait_group %0;\n" ::"n"(N)); }

__device__ __forceinline__ uint32_t h2u(__half2 h) { return *reinterpret_cast<uint32_t*>(&h); }

// ---------------- 0) fp32 -> fp16 conversion pass ----------------
__global__ __launch_bounds__(256) void convert_kernel(const float* __restrict__ x,
                                                      const float* __restrict__ wq,
                                                      const float* __restrict__ wk,
                                                      const float* __restrict__ wv,
                                                      const float* __restrict__ wg,
                                                      const float* __restrict__ wo) {
    const int z = blockIdx.y;
    const float* src;
    __half* dst;
    int cnt;
    if (z == 0) { src = x; dst = g_x16; cnt = NB * NSEQ * CQ; }
    else if (z == 1) { src = wq; dst = g_w16; cnt = CQ * CQ; }
    else if (z == 2) { src = wk; dst = g_w16 + CQ * CQ; cnt = CQ * CQ; }
    else if (z == 3) { src = wv; dst = g_w16 + 2 * CQ * CQ; cnt = CQ * CQ; }
    else if (z == 4) { src = wg; dst = g_w16 + 3 * CQ * CQ; cnt = CQ * CQ; }
    else { src = wo; dst = g_w16 + 4 * CQ * CQ; cnt = CQ * CQ; }
    const int idx = (blockIdx.x * 256 + threadIdx.x) * 8;
    if (idx < cnt) {
        float4 v0 = *reinterpret_cast<const float4*>(src + idx);
        float4 v1 = *reinterpret_cast<const float4*>(src + idx + 4);
        __half2* d2 = reinterpret_cast<__half2*>(dst + idx);
        d2[0] = __floats2half2_rn(v0.x, v0.y);
        d2[1] = __floats2half2_rn(v0.z, v0.w);
        d2[2] = __floats2half2_rn(v1.x, v1.y);
        d2[3] = __floats2half2_rn(v1.z, v1.w);
    }
}

// ---------------- S-stage cp.async pipelined fp16 GEMM core (BK=64) ----------------
// C[128 x 64] = A[M,K] * B^T, A/B fp16 row-major [*, K]. K multiple of 64.
// 256 threads, 4x2 warps, warp tile 32x32. acc[32] = [m<2][n<4][4].
#define GSTR 72
#define GA_BYTES (128 * GSTR * 2)  // 18432
#define GB_BYTES (64 * GSTR * 2)   // 9216
#define PROJ_SMEM (3 * (GA_BYTES + GB_BYTES))   // S=3: 82944
#define FINAL_SMEM (2 * (GA_BYTES + GB_BYTES))  // S=2: 55296

template <int S>
__device__ __forceinline__ void gemm128x64h(const __half* __restrict__ A, int lda,
                                            const __half* __restrict__ Bp, int ldb, int K,
                                            int row0, int col0, float* acc, __half* dsm) {
    const int tid = threadIdx.x, lane = tid & 31, wid = tid >> 5;
    const int wm = (wid >> 1) << 5, wn = (wid & 1) << 5;
    const int mi = lane >> 3;
    const uint32_t sb = (uint32_t)__cvta_generic_to_shared(dsm);
    const int NK = K >> 6;

#pragma unroll
    for (int i = 0; i < 32; i++) acc[i] = 0.f;

    const int lr = tid >> 3, lch = tid & 7;
    const __half* aSrc = A + (size_t)(row0 + lr) * lda + lch * 8;
    const __half* bSrc = Bp + (size_t)(col0 + lr) * ldb + lch * 8;
    const uint32_t sAd = (lr * GSTR + lch * 8) * 2;

    auto issue = [&](int stage, int kt) {
        const int k0 = kt << 6;
        const uint32_t ab = sb + stage * GA_BYTES;
        const uint32_t bb = sb + S * GA_BYTES + stage * GB_BYTES;
#pragma unroll
        for (int t = 0; t < 4; t++)
            cp16(ab + sAd + t * 32 * GSTR * 2, aSrc + (size_t)t * 32 * lda + k0);
#pragma unroll
        for (int t = 0; t < 2; t++)
            cp16(bb + sAd + t * 32 * GSTR * 2, bSrc + (size_t)t * 32 * ldb + k0);
        cp_commit();
    };

#pragma unroll
    for (int s = 0; s < S - 1; s++) issue(s, s);

    for (int kt = 0; kt < NK; kt++) {
        cp_wait<S - 2>();
        __syncthreads();
        if (kt + S - 1 < NK) issue((kt + S - 1) % S, kt + S - 1);
        else cp_commit();  // keep per-thread group count uniform

        const uint32_t ab = sb + (kt % S) * GA_BYTES;
        const uint32_t bb = sb + S * GA_BYTES + (kt % S) * GB_BYTES;
#pragma unroll
        for (int ks = 0; ks < 4; ks++) {
            uint32_t a[2][4], b[2][4];
#pragma unroll
            for (int mf = 0; mf < 2; mf++) {
                int row = wm + mf * 16 + (lane & 7) + ((mi & 1) << 3);
                int kch = ks * 2 + (mi >> 1);
                ldm4(a[mf][0], a[mf][1], a[mf][2], a[mf][3], ab + (row * GSTR + kch * 8) * 2);
            }
#pragma unroll
            for (int g = 0; g < 2; g++) {
                int row = wn + g * 16 + (lane & 7) + ((mi >> 1) << 3);
                int kch = ks * 2 + (mi & 1);
                ldm4(b[g][0], b[g][1], b[g][2], b[g][3], bb + (row * GSTR + kch * 8) * 2);
            }
#pragma unroll
            for (int mf = 0; mf < 2; mf++)
#pragma unroll
                for (int g = 0; g < 2; g++) {
                    mma16(acc + (mf * 4 + g * 2) * 4, a[mf], b[g]);
                    mma16(acc + (mf * 4 + g * 2 + 1) * 4, a[mf], b[g] + 2);
                }
        }
        __syncthreads();
    }
    cp_wait<0>();
}

// ---------------- 1) fused Q/K/V/Gate projections (R10 config: S=3, 2 CTA/SM) ------
__global__ __launch_bounds__(256, 2) void proj_kernel(const float* __restrict__ bq,
                                                      const float* __restrict__ bg,
                                                      const float* __restrict__ gbias) {
    extern __shared__ __half hsm[];
    const int z = blockIdx.z;
    const __half* W = g_w16 + (size_t)z * CQ * CQ;
    const int row0 = blockIdx.y * 128, col0 = blockIdx.x * 64;
    float acc[32];
    gemm128x64h<3>(g_x16, CQ, W, CQ, CQ, row0, col0, acc, hsm);

    const int lane = threadIdx.x & 31, wid = threadIdx.x >> 5;
    const int wm = (wid >> 1) << 5, wn = (wid & 1) << 5;
#pragma unroll
    for (int m = 0; m < 2; m++)
#pragma unroll
        for (int n = 0; n < 4; n++) {
            const float* a4 = acc + (m * 4 + n) * 4;
            const int r = row0 + wm + m * 16 + (lane >> 2);
            const int c = col0 + wn + n * 8 + ((lane & 3) << 1);
            const int b = r >> 10, nn0 = r & 1023, nn1 = (r + 8) & 1023;
            if (z == 3) {
                const float bb = bg[c] + gbias[c], bb1 = bg[c + 1] + gbias[c + 1];
                float2 g0 = make_float2(1.f / (1.f + __expf(-(a4[0] + bb))),
                                        1.f / (1.f + __expf(-(a4[1] + bb1))));
                float2 g1 = make_float2(1.f / (1.f + __expf(-(a4[2] + bb))),
                                        1.f / (1.f + __expf(-(a4[3] + bb1))));
                *reinterpret_cast<float2*>(&g_gate[(size_t)r * CQ + c]) = g0;
                *reinterpret_cast<float2*>(&g_gate[(size_t)(r + 8) * CQ + c]) = g1;
            } else {
                const int h = c >> 6, d = c & 63;
                __half* dst = (z == 0) ? g_q16 : (z == 1) ? g_k16 : g_v16;
                float v0 = a4[0], v1 = a4[1], v2 = a4[2], v3 = a4[3];
                if (z == 0) {
                    v0 = (v0 + bq[c]) * 0.125f;
                    v1 = (v1 + bq[c + 1]) * 0.125f;
                    v2 = (v2 + bq[c]) * 0.125f;
                    v3 = (v3 + bq[c + 1]) * 0.125f;
                }
                __half2* p0 = reinterpret_cast<__half2*>(
                    dst + ((size_t)((b * NH + h) * NSEQ) + nn0) * HD + d);
                __half2* p1 = reinterpret_cast<__half2*>(
                    dst + ((size_t)((b * NH + h) * NSEQ) + nn1) * HD + d);
                *p0 = __floats2half2_rn(v0, v1);
                *p1 = __floats2half2_rn(v2, v3);
            }
        }
}

// ---------------- 2) fused flash attention (exact R10 version) ----------------
// Half-tile double-buffered bias stream + single-buffered K/V, 2 CTA/SM.
// smem: bias 2 x [8 warps][16][72] fp32 = 2x36864 | K 18432 | V 18432 = 110592 B.
// Q tile (prologue only) aliases bias buffer 0.
#define BIAS_HALF_BYTES (8 * 16 * 72 * 4)  // 36864
#define KV_BYTES (128 * 72 * 2)            // 18432
#define FL_K (2 * BIAS_HALF_BYTES)
#define FL_V (FL_K + KV_BYTES)
#define FLASH_SMEM (FL_V + KV_BYTES)

__global__ __launch_bounds__(256, 2) void flash_kernel(const float* __restrict__ attn_bias) {
    extern __shared__ float fsm[];
    __half* Qs = reinterpret_cast<__half*>(fsm);  // aliases bias buffer 0, prologue only
    const uint32_t sb = (uint32_t)__cvta_generic_to_shared(fsm);
    const uint32_t Qb = sb, Kb = sb + FL_K, Vb = sb + FL_V;

    const int bh = blockIdx.y;
    const int qt = blockIdx.x;
    const int b = bh >> 3, h = bh & 7;
    const int tid = threadIdx.x, lane = tid & 31, warp = tid >> 5;
    const int mi = lane >> 3;
    const __half* qptr = g_q16 + (size_t)bh * NSEQ * HD + (size_t)qt * 128 * HD;
    const __half* kptr = g_k16 + (size_t)bh * NSEQ * HD;
    const __half* vptr = g_v16 + (size_t)bh * NSEQ * HD;
    const float* bias = attn_bias + (size_t)bh * NSEQ * NSEQ + (size_t)qt * 128 * NSEQ;

    auto issueKV = [&](int kt) {
#pragma unroll
        for (int t = 0; t < 4; t++) {
            int idx = tid + t * 256;
            int r = idx >> 3, ch = idx & 7;
            cp16(Kb + (r * 72 + ch * 8) * 2, kptr + (size_t)(kt * 128 + r) * HD + ch * 8);
        }
#pragma unroll
        for (int t = 0; t < 4; t++) {
            int idx = tid + t * 256;
            int r = idx >> 3, ch = idx & 7;
            cp16(Vb + (r * 72 + ch * 8) * 2, vptr + (size_t)(kt * 128 + r) * HD + ch * 8);
        }
        cp_commit();
    };
    const float* bias_warp = bias + (size_t)(warp * 16) * NSEQ;
    auto issueBiasHalf = [&](int buf, int kt, int half) {
        const uint32_t dst = sb + buf * BIAS_HALF_BYTES + warp * 4608;
        const float* src = bias_warp + kt * 128 + half * 64;
#pragma unroll
        for (int i = 0; i < 8; i++) {
            int idx = i * 32 + lane;
            int r = idx >> 4, ch = idx & 15;
            cp16(dst + r * 288 + ch * 16, src + (size_t)r * NSEQ + ch * 4);
        }
        cp_commit();
    };

    // K/V of tile 0 in flight during the Q prologue
    issueKV(0);

    // prologue: Q tile -> smem -> fragments
#pragma unroll
    for (int t = 0; t < 4; t++) {
        int idx = tid + t * 256;
        int r = idx >> 3, ch = idx & 7;
        *reinterpret_cast<uint4*>(&Qs[r * 72 + ch * 8]) =
            *reinterpret_cast<const uint4*>(qptr + r * HD + ch * 8);
    }
    __syncthreads();

    uint32_t qf[4][4];
#pragma unroll
    for (int ks = 0; ks < 4; ks++) {
        int row = warp * 16 + (lane & 7) + ((mi & 1) << 3);
        int kch = ks * 2 + (mi >> 1);
        ldm4(qf[ks][0], qf[ks][1], qf[ks][2], qf[ks][3], Qb + (row * 72 + kch * 8) * 2);
    }
    __syncthreads();  // Q fragments extracted; bias buffer 0 may be overwritten

    issueBiasHalf(0, 0, 0);

    float l0 = 0.f, l1 = 0.f;
    float acc_o[8][4];
#pragma unroll
    for (int n = 0; n < 8; n++)
#pragma unroll
        for (int j = 0; j < 4; j++) acc_o[n][j] = 0.f;

    const int rl = lane >> 2;

    for (int kt = 0; kt < 8; kt++) {
        // wait: biasH0(kt) + KV(kt); barrier so every warp's cp.async chunks are visible
        cp_wait<0>();
        __syncthreads();

        // biasH1(kt) streams behind half-0 compute
        issueBiasHalf(1, kt, 1);

#pragma unroll
        for (int half = 0; half < 2; half++) {
            // S = Q K^T over 64 keys
            float s[8][4];
#pragma unroll
            for (int n = 0; n < 8; n++)
#pragma unroll
                for (int j = 0; j < 4; j++) s[n][j] = 0.f;
#pragma unroll
            for (int ks = 0; ks < 4; ks++) {
                const int kch = ks * 2 + (mi & 1);
#pragma unroll
                for (int nb = 0; nb < 4; nb++) {
                    uint32_t b0, b1, b2, b3;
                    int row = half * 64 + nb * 16 + (lane & 7) + ((mi >> 1) << 3);
                    ldm4(b0, b1, b2, b3, Kb + (row * 72 + kch * 8) * 2);
                    uint32_t bA[2] = {b0, b1}, bB[2] = {b2, b3};
                    mma16(s[2 * nb], qf[ks], bA);
                    mma16(s[2 * nb + 1], qf[ks], bB);
                }
            }

            // bias + exp; P fragments packed in registers
            const float* bw = fsm + half * (BIAS_HALF_BYTES / 4) + warp * 1152;
            uint32_t pf[4][4];
            float rs0 = 0.f, rs1 = 0.f;
#pragma unroll
            for (int n = 0; n < 8; n++) {
                const int c = n * 8 + ((lane & 3) << 1);
                float2 b0 = *reinterpret_cast<const float2*>(bw + rl * 72 + c);
                float2 b1 = *reinterpret_cast<const float2*>(bw + (rl + 8) * 72 + c);
                float p0 = __expf(s[n][0] + b0.x);
                float p1 = __expf(s[n][1] + b0.y);
                float p2 = __expf(s[n][2] + b1.x);
                float p3 = __expf(s[n][3] + b1.y);
                rs0 += p0 + p1;
                rs1 += p2 + p3;
                const uint32_t h01 = h2u(__floats2half2_rn(p0, p1));
                const uint32_t h23 = h2u(__floats2half2_rn(p2, p3));
                if ((n & 1) == 0) {
                    pf[n >> 1][0] = h01;
                    pf[n >> 1][1] = h23;
                } else {
                    pf[n >> 1][2] = h01;
                    pf[n >> 1][3] = h23;
                }
            }
            l0 += rs0;
            l1 += rs1;

            // O += P V over these 64 keys
#pragma unroll
            for (int ks2 = 0; ks2 < 4; ks2++) {
                int srow = half * 64 + ks2 * 16 + (lane & 7) + ((mi & 1) << 3);
#pragma unroll
                for (int nb = 0; nb < 4; nb++) {
                    uint32_t b0, b1, b2, b3;
                    int nch = nb * 2 + (mi >> 1);
                    ldm4t(b0, b1, b2, b3, Vb + (srow * 72 + nch * 8) * 2);
                    uint32_t bA[2] = {b0, b1}, bB[2] = {b2, b3};
                    mma16(acc_o[2 * nb], pf[ks2], bA);
                    mma16(acc_o[2 * nb + 1], pf[ks2], bB);
                }
            }

            if (half == 0) {
                // wait biasH1(kt); warp-private -> no block sync needed
                cp_wait<0>();
                __syncwarp();
                // stream biasH0(kt+1) behind half-1 compute
                if (kt < 7) issueBiasHalf(0, kt + 1, 0);
            }
        }

        __syncthreads();  // all warps done reading K/V(kt)
        if (kt < 7) issueKV(kt + 1);
    }

    // final l reduction (4 lanes per row)
    l0 += __shfl_xor_sync(0xffffffffu, l0, 1);
    l0 += __shfl_xor_sync(0xffffffffu, l0, 2);
    l1 += __shfl_xor_sync(0xffffffffu, l1, 1);
    l1 += __shfl_xor_sync(0xffffffffu, l1, 2);

    const float inv0 = 1.f / l0, inv1 = 1.f / l1;
    const int qg = qt * 128 + warp * 16 + rl;
#pragma unroll
    for (int n = 0; n < 8; n++) {
        int c = h * HD + n * 8 + ((lane & 3) << 1);
        *reinterpret_cast<__half2*>(&g_o16[(size_t)(b * NSEQ + qg) * CQ + c]) =
            __floats2half2_rn(acc_o[n][0] * inv0, acc_o[n][1] * inv0);
        *reinterpret_cast<__half2*>(&g_o16[(size_t)(b * NSEQ + qg + 8) * CQ + c]) =
            __floats2half2_rn(acc_o[n][2] * inv1, acc_o[n][3] * inv1);
    }
}

// ---------------- 3) out = (o @ Wo^T + bo) * gate (R12 config: S=2, 3 CTA/SM) ------
__global__ __launch_bounds__(256, 3) void final_kernel(const float* __restrict__ bo,
                                                       float* __restrict__ out) {
    extern __shared__ __half hsm[];
    const int row0 = blockIdx.y * 128, col0 = blockIdx.x * 64;
    float acc[32];
    gemm128x64h<2>(g_o16, CQ, g_w16 + 4 * CQ * CQ, CQ, CQ, row0, col0, acc, hsm);

    const int lane = threadIdx.x & 31, wid = threadIdx.x >> 5;
    const int wm = (wid >> 1) << 5, wn = (wid & 1) << 5;
#pragma unroll
    for (int m = 0; m < 2; m++)
#pragma unroll
        for (int n = 0; n < 4; n++) {
            const float* a4 = acc + (m * 4 + n) * 4;
            const int r = row0 + wm + m * 16 + (lane >> 2);
            const int c = col0 + wn + n * 8 + ((lane & 3) << 1);
            const float b0 = bo[c], b1 = bo[c + 1];
            float2 o0 = make_float2((a4[0] + b0) * g_gate[(size_t)r * CQ + c],
                                    (a4[1] + b1) * g_gate[(size_t)r * CQ + c + 1]);
            float2 o1 = make_float2((a4[2] + b0) * g_gate[(size_t)(r + 8) * CQ + c],
                                    (a4[3] + b1) * g_gate[(size_t)(r + 8) * CQ + c + 1]);
            *reinterpret_cast<float2*>(&out[(size_t)r * CQ + c]) = o0;
            *reinterpret_cast<float2*>(&out[(size_t)(r + 8) * CQ + c]) = o1;
        }
}

// ---------------- launch ----------------
extern "C" void kernel_launch(void* const* d_in, const int* in_sizes, int n_in,
                              void* d_out, int out_size) {
    const float* q_x = (const float*)d_in[0];
    const float* attn_bias = (const float*)d_in[1];
    const float* Wq = (const float*)d_in[2];
    const float* bq = (const float*)d_in[3];
    const float* Wk = (const float*)d_in[4];
    const float* Wv = (const float*)d_in[5];
    const float* Wo = (const float*)d_in[6];
    const float* bo = (const float*)d_in[7];
    const float* Wg = (const float*)d_in[8];
    const float* bg = (const float*)d_in[9];
    const float* gbias = (const float*)d_in[10];
    float* out = (float*)d_out;

    cudaFuncSetAttribute(flash_kernel, cudaFuncAttributeMaxDynamicSharedMemorySize, FLASH_SMEM);
    cudaFuncSetAttribute(proj_kernel, cudaFuncAttributeMaxDynamicSharedMemorySize, PROJ_SMEM);
    cudaFuncSetAttribute(final_kernel, cudaFuncAttributeMaxDynamicSharedMemorySize, FINAL_SMEM);

    convert_kernel<<<dim3(1024, 6), 256>>>(q_x, Wq, Wk, Wv, Wg, Wo);
    proj_kernel<<<dim3(CQ / 64, (NB * NSEQ) / 128, 4), 256, PROJ_SMEM>>>(bq, bg, gbias);
    flash_kernel<<<dim3(NSEQ / 128, NB * NH), 256, FLASH_SMEM>>>(attn_bias);
    final_kernel<<<dim3(CQ / 64, (NB * NSEQ) / 128), 256, FINAL_SMEM>>>(bo, out);
}